// round 1
// baseline (speedup 1.0000x reference)
#include <cuda_runtime.h>
#include <cstdint>

// IGNN step, fp32 FFMA baseline.
//   edge_kernel: per 64-edge tile, fused  X=[e|h_recv|h_send] -> relu(X@We1+be1)
//                -> edges_new=(..@We2+be2)*ae -> F=[edges_new|h_recv|h_send]
//                -> relu(F@Wf1+bf1) -> effects=..@Wf2+bf2 -> atomicAdd into agg[recv]
//   node_kernel: per 64-node tile, Y=[nodes|agg] -> relu(Y@Wn1+bn1) -> dn=..@Wn2+bn2
//                -> out = nodes + dn*active
// Scratch agg lives in a __device__ global (no allocations), zeroed each launch.

#define THREADS 256
#define XS_LD 388   // 384 + pad (mult of 4, odd-ish bank offset mod 32 = 4)
#define HS_LD 260   // 256 + pad

__device__ float g_agg[50000 * 128];

__global__ void zero_agg_kernel(int n4) {
    int i = blockIdx.x * blockDim.x + threadIdx.x;
    int stride = gridDim.x * blockDim.x;
    float4* p = (float4*)g_agg;
    float4 z = make_float4(0.f, 0.f, 0.f, 0.f);
    for (int idx = i; idx < n4; idx += stride) p[idx] = z;
}

// C[64 x NC] = A(smem)[64 x K] @ W(gmem)[K x NC] + bias, accumulators stay in
// registers. 256 threads as 16x16; each thread owns 4 rows x (NC/16) cols.
// Ws is a 4096-float smem staging buffer for weight K-chunks.
template<int K, int NC>
__device__ __forceinline__ void gemm64(
    const float* __restrict__ Ax, int lda,
    const float* __restrict__ Wg,
    const float* __restrict__ bias,
    float* __restrict__ Ws,
    float (&acc)[4][NC / 16],
    int tx, int ty)
{
    constexpr int CT = NC / 16;
    constexpr int KCHUNK = 4096 / NC;
    const int c0 = tx * CT;
    const int tid = ty * 16 + tx;

#pragma unroll
    for (int j = 0; j < CT; j++) {
        float b = bias[c0 + j];
#pragma unroll
        for (int i = 0; i < 4; i++) acc[i][j] = b;
    }

    for (int kc = 0; kc < K; kc += KCHUNK) {
        __syncthreads();
        // stage W chunk [KCHUNK x NC] : 1024 float4 by 256 threads
#pragma unroll
        for (int l = 0; l < 4; l++) {
            int idx = tid + l * THREADS;
            int kk = idx / (NC / 4);
            int cc = idx % (NC / 4);
            ((float4*)Ws)[idx] =
                ((const float4*)Wg)[(size_t)(kc + kk) * (NC / 4) + cc];
        }
        __syncthreads();
#pragma unroll 4
        for (int kk = 0; kk < KCHUNK; kk++) {
            float a[4];
#pragma unroll
            for (int i = 0; i < 4; i++) a[i] = Ax[(ty * 4 + i) * lda + kc + kk];
#pragma unroll
            for (int j4 = 0; j4 < CT / 4; j4++) {
                float4 b4 = *(const float4*)&Ws[kk * NC + c0 + j4 * 4];
#pragma unroll
                for (int i = 0; i < 4; i++) {
                    acc[i][4 * j4 + 0] = fmaf(a[i], b4.x, acc[i][4 * j4 + 0]);
                    acc[i][4 * j4 + 1] = fmaf(a[i], b4.y, acc[i][4 * j4 + 1]);
                    acc[i][4 * j4 + 2] = fmaf(a[i], b4.z, acc[i][4 * j4 + 2]);
                    acc[i][4 * j4 + 3] = fmaf(a[i], b4.w, acc[i][4 * j4 + 3]);
                }
            }
        }
    }
}

// smem floats: Xs 64*388 + Hs 64*260 + Ws 4096 + rcv 64 + ae 64 = 45696 (182784 B)
#define EDGE_SMEM_FLOATS (64 * XS_LD + 64 * HS_LD + 4096 + 64 + 64)

__global__ void __launch_bounds__(THREADS, 1) edge_kernel(
    const float* __restrict__ nodes, const float* __restrict__ edges,
    const int* __restrict__ senders, const int* __restrict__ receivers,
    const float* __restrict__ active_edges,
    const float* __restrict__ We1, const float* __restrict__ be1,
    const float* __restrict__ We2, const float* __restrict__ be2,
    const float* __restrict__ Wf1, const float* __restrict__ bf1,
    const float* __restrict__ Wf2, const float* __restrict__ bf2,
    float* __restrict__ out_edges, int E)
{
    extern __shared__ float sm[];
    float* Xs = sm;                      // [64][XS_LD]
    float* Hs = Xs + 64 * XS_LD;         // [64][HS_LD]
    float* Ws = Hs + 64 * HS_LD;         // [4096]
    int*   rcv = (int*)(Ws + 4096);      // [64]
    float* ae  = (float*)(rcv + 64);     // [64]

    const int tid = threadIdx.x;
    const int tx = tid & 15, ty = tid >> 4;
    const long long e0 = (long long)blockIdx.x * 64;

    if (tid < 64) {
        long long er = e0 + tid;
        bool ok = er < E;
        rcv[tid] = ok ? receivers[er] : 0;
        ae[tid]  = ok ? active_edges[er] : 0.f;
    }
    {
        // Gather/stage X = [edge | h_recv | h_send] : 4 threads per row, 8 f4 each per source
        int r = tid >> 2, c4 = tid & 3;
        long long er = e0 + r;
        bool ok = er < E;
        int ridx = ok ? receivers[er] : 0;
        int sidx = ok ? senders[er] : 0;
        const float4* E4 = (const float4*)edges;
        const float4* N4 = (const float4*)nodes;
        float4 z = make_float4(0.f, 0.f, 0.f, 0.f);
#pragma unroll
        for (int j = 0; j < 8; j++) {
            int cc = c4 + j * 4;   // float4 col 0..31
            float4 ve = ok ? E4[(size_t)er * 32 + cc] : z;
            float4 vr = ok ? N4[(size_t)ridx * 32 + cc] : z;
            float4 vs = ok ? N4[(size_t)sidx * 32 + cc] : z;
            *(float4*)&Xs[r * XS_LD + cc * 4]       = ve;
            *(float4*)&Xs[r * XS_LD + 128 + cc * 4] = vr;
            *(float4*)&Xs[r * XS_LD + 256 + cc * 4] = vs;
        }
    }
    // (gemm64 starts with __syncthreads -> staging visible)

    float acc1[4][16];
    float acc2[4][8];

    // --- stage 1: H1 = relu(X @ We1 + be1) ---
    gemm64<384, 256>(Xs, XS_LD, We1, be1, Ws, acc1, tx, ty);
#pragma unroll
    for (int i = 0; i < 4; i++)
#pragma unroll
        for (int j = 0; j < 16; j++)
            Hs[(ty * 4 + i) * HS_LD + tx * 16 + j] = fmaxf(acc1[i][j], 0.f);

    // --- stage 2: edges_new = (H1 @ We2 + be2) * active_edges ---
    gemm64<256, 128>(Hs, HS_LD, We2, be2, Ws, acc2, tx, ty);
#pragma unroll
    for (int i = 0; i < 4; i++) {
        int r = ty * 4 + i;
        long long er = e0 + r;
        float m = ae[r];
#pragma unroll
        for (int j = 0; j < 8; j++) {
            int c = tx * 8 + j;
            float v = acc2[i][j] * m;
            if (er < E) out_edges[(size_t)er * 128 + c] = v;
            Xs[r * XS_LD + c] = v;   // F = [edges_new | h_recv | h_send]
        }
    }

    // --- stage 3: H2 = relu(F @ Wf1 + bf1) ---
    gemm64<384, 256>(Xs, XS_LD, Wf1, bf1, Ws, acc1, tx, ty);
#pragma unroll
    for (int i = 0; i < 4; i++)
#pragma unroll
        for (int j = 0; j < 16; j++)
            Hs[(ty * 4 + i) * HS_LD + tx * 16 + j] = fmaxf(acc1[i][j], 0.f);

    // --- stage 4: effects = H2 @ Wf2 + bf2 ; scatter-add to agg[recv] ---
    gemm64<256, 128>(Hs, HS_LD, Wf2, bf2, Ws, acc2, tx, ty);
#pragma unroll
    for (int i = 0; i < 4; i++) {
        int r = ty * 4 + i;
        long long er = e0 + r;
        if (er < E) {
            float* arow = &g_agg[(size_t)rcv[r] * 128];
#pragma unroll
            for (int j = 0; j < 8; j++)
                atomicAdd(&arow[tx * 8 + j], acc2[i][j]);
        }
    }
}

// smem floats: Xs 64*260 + Hs 64*260 + Ws 4096 + an 64 = 37440 (149760 B)
#define NODE_SMEM_FLOATS (64 * HS_LD + 64 * HS_LD + 4096 + 64)

__global__ void __launch_bounds__(THREADS, 1) node_kernel(
    const float* __restrict__ nodes,
    const float* __restrict__ active_nodes,
    const float* __restrict__ Wn1, const float* __restrict__ bn1,
    const float* __restrict__ Wn2, const float* __restrict__ bn2,
    float* __restrict__ out_nodes, int N)
{
    extern __shared__ float sm[];
    float* Xs = sm;                      // [64][HS_LD] : [nodes | agg]
    float* Hs = Xs + 64 * HS_LD;         // [64][HS_LD]
    float* Ws = Hs + 64 * HS_LD;         // [4096]
    float* an = Ws + 4096;               // [64]

    const int tid = threadIdx.x;
    const int tx = tid & 15, ty = tid >> 4;
    const long long n0 = (long long)blockIdx.x * 64;

    if (tid < 64) {
        long long row = n0 + tid;
        an[tid] = (row < N) ? active_nodes[row] : 0.f;
    }
    {
        int r = tid >> 2, c4 = tid & 3;
        long long row = n0 + r;
        bool ok = row < N;
        const float4* N4 = (const float4*)nodes;
        const float4* A4 = (const float4*)g_agg;
        float4 z = make_float4(0.f, 0.f, 0.f, 0.f);
#pragma unroll
        for (int j = 0; j < 16; j++) {
            int cc = c4 + j * 4;   // float4 col 0..63
            float4 v;
            if (!ok)          v = z;
            else if (cc < 32) v = N4[(size_t)row * 32 + cc];
            else              v = A4[(size_t)row * 32 + (cc - 32)];
            *(float4*)&Xs[r * HS_LD + cc * 4] = v;
        }
    }

    float acc1[4][16];
    gemm64<256, 256>(Xs, HS_LD, Wn1, bn1, Ws, acc1, tx, ty);
#pragma unroll
    for (int i = 0; i < 4; i++)
#pragma unroll
        for (int j = 0; j < 16; j++)
            Hs[(ty * 4 + i) * HS_LD + tx * 16 + j] = fmaxf(acc1[i][j], 0.f);

    float acc2[4][8];
    gemm64<256, 128>(Hs, HS_LD, Wn2, bn2, Ws, acc2, tx, ty);
#pragma unroll
    for (int i = 0; i < 4; i++) {
        int r = ty * 4 + i;
        long long row = n0 + r;
        if (row < N) {
            float m = an[r];
#pragma unroll
            for (int j = 0; j < 8; j++) {
                int c = tx * 8 + j;
                out_nodes[(size_t)row * 128 + c] =
                    Xs[r * HS_LD + c] + acc2[i][j] * m;
            }
        }
    }
}

extern "C" void kernel_launch(void* const* d_in, const int* in_sizes, int n_in,
                              void* d_out, int out_size)
{
    const float* nodes        = (const float*)d_in[0];
    const float* edges        = (const float*)d_in[1];
    const int*   senders      = (const int*)d_in[2];
    const int*   receivers    = (const int*)d_in[3];
    const float* active_nodes = (const float*)d_in[4];
    const float* active_edges = (const float*)d_in[5];
    const float* We1 = (const float*)d_in[6];
    const float* be1 = (const float*)d_in[7];
    const float* We2 = (const float*)d_in[8];
    const float* be2 = (const float*)d_in[9];
    const float* Wf1 = (const float*)d_in[10];
    const float* bf1 = (const float*)d_in[11];
    const float* Wf2 = (const float*)d_in[12];
    const float* bf2 = (const float*)d_in[13];
    const float* Wn1 = (const float*)d_in[14];
    const float* bn1 = (const float*)d_in[15];
    const float* Wn2 = (const float*)d_in[16];
    const float* bn2 = (const float*)d_in[17];

    const int E = in_sizes[2];   // senders
    const int N = in_sizes[4];   // active_nodes

    float* out_nodes = (float*)d_out;
    float* out_edges = out_nodes + (size_t)N * 128;

    const size_t edge_smem = EDGE_SMEM_FLOATS * sizeof(float);
    const size_t node_smem = NODE_SMEM_FLOATS * sizeof(float);
    cudaFuncSetAttribute(edge_kernel, cudaFuncAttributeMaxDynamicSharedMemorySize,
                         (int)edge_smem);
    cudaFuncSetAttribute(node_kernel, cudaFuncAttributeMaxDynamicSharedMemorySize,
                         (int)node_smem);

    zero_agg_kernel<<<256, 256>>>(N * 128 / 4);

    int eblocks = (E + 63) / 64;
    edge_kernel<<<eblocks, THREADS, edge_smem>>>(
        nodes, edges, senders, receivers, active_edges,
        We1, be1, We2, be2, Wf1, bf1, Wf2, bf2,
        out_edges, E);

    int nblocks = (N + 63) / 64;
    node_kernel<<<nblocks, THREADS, node_smem>>>(
        nodes, active_nodes, Wn1, bn1, Wn2, bn2, out_nodes, N);
}

// round 4
// speedup vs baseline: 5.3844x; 5.3844x over previous
#include <cuda_runtime.h>
#include <cstdint>

// ============================================================================
// IGNN step via mma.sync.m16n8k8 tf32 (sm_100-compatible tensor path).
// edge_kernel: 64 edges/CTA, 256 thr (8 warps, 4x2), 4 chained GEMMs:
//   X[64x384]@We1 -> relu -> @We2 -> edges_new -> F[64x384]@Wf1 -> relu
//   -> @Wf2 -> atomicAdd into g_agg[recv]
// node_kernel: [nodes|agg][64x256]@Wn1 -> relu -> @Wn2 -> residual out.
// Weights pre-packed fragment-major in g_wimg; chunks cp.async double-buffered.
// ============================================================================

#define THREADS 256
#define NN 50000

#define OFF_WE1 0
#define OFF_WE2 98304
#define OFF_WF1 131072
#define OFF_WF2 229376
#define OFF_WN1 262144
#define OFF_WN2 327680
#define WIMG_TOTAL 360448

__device__ float g_wimg[WIMG_TOTAL];
__device__ float g_agg[(size_t)NN * 128];

static __device__ __forceinline__ uint32_t cvt_tf32_u(float x) {
    uint32_t u; asm("cvt.rna.tf32.f32 %0, %1;" : "=r"(u) : "f"(x)); return u;
}
static __device__ __forceinline__ float cvt_tf32_f(float x) {
    return __uint_as_float(cvt_tf32_u(x));
}
static __device__ __forceinline__ uint32_t smem_u32(const void* p) {
    uint32_t a;
    asm("{ .reg .u64 t; cvta.to.shared.u64 t, %1; cvt.u32.u64 %0, t; }"
        : "=r"(a) : "l"(p));
    return a;
}
static __device__ __forceinline__ unsigned long long gptr(const void* p) {
    unsigned long long g;
    asm("cvta.to.global.u64 %0, %1;" : "=l"(g) : "l"(p));
    return g;
}

#define CP_ASYNC16(dst, src) \
    asm volatile("cp.async.cg.shared.global [%0], [%1], 16;" :: "r"(dst), "l"(src))
#define CP_COMMIT() asm volatile("cp.async.commit_group;" ::: "memory")
#define CP_WAIT1()  asm volatile("cp.async.wait_group 1;" ::: "memory")
#define CP_WAIT0()  asm volatile("cp.async.wait_group 0;" ::: "memory")

static __device__ __forceinline__ void mma_tf32(float (&d)[4], const uint32_t (&a)[4],
                                                uint32_t b0, uint32_t b1) {
    asm volatile(
        "mma.sync.aligned.m16n8k8.row.col.f32.tf32.tf32.f32 "
        "{%0,%1,%2,%3}, {%4,%5,%6,%7}, {%8,%9}, {%0,%1,%2,%3};"
        : "+f"(d[0]), "+f"(d[1]), "+f"(d[2]), "+f"(d[3])
        : "r"(a[0]), "r"(a[1]), "r"(a[2]), "r"(a[3]), "r"(b0), "r"(b1));
}

// ---------------- prep: fragment-major weight image + zero agg ---------------
// image layout per GEMM: block = (s_glob * P + p), 128 floats per block:
//   float4 at lane*4: {W[k0+l%4][n0+l/4], W[k0+4+l%4][n0+l/4],
//                      W[k0+l%4][n0+8+l/4], W[k0+4+l%4][n0+8+l/4]}
//   k0 = s_glob*8, n0 = p*16, P = NC/16.
static __device__ __forceinline__ void prep_one(const float* __restrict__ W,
                                                float* __restrict__ dst,
                                                int NC, int l) {
    int q = l & 3, lane = (l >> 2) & 31, blk = l >> 7;
    int P = NC / 16;
    int p = blk % P, s = blk / P;
    int k = s * 8 + ((q & 1) ? 4 : 0) + (lane & 3);
    int n = p * 16 + ((q >> 1) ? 8 : 0) + (lane >> 2);
    dst[l] = __uint_as_float(cvt_tf32_u(W[(size_t)k * NC + n]));
}

__global__ void prep_zero_kernel(
    const float* We1, const float* We2, const float* Wf1,
    const float* Wf2, const float* Wn1, const float* Wn2, int nfour)
{
    int idx = blockIdx.x * blockDim.x + threadIdx.x;
    float4 z = make_float4(0.f, 0.f, 0.f, 0.f);
    for (int i = idx; i < nfour; i += gridDim.x * blockDim.x)
        ((float4*)g_agg)[i] = z;
    if (idx < 98304)       prep_one(We1, g_wimg + OFF_WE1, 256, idx);
    else if (idx < 131072) prep_one(We2, g_wimg + OFF_WE2, 128, idx - 98304);
    else if (idx < 229376) prep_one(Wf1, g_wimg + OFF_WF1, 256, idx - 131072);
    else if (idx < 262144) prep_one(Wf2, g_wimg + OFF_WF2, 128, idx - 229376);
    else if (idx < 327680) prep_one(Wn1, g_wimg + OFF_WN1, 256, idx - 262144);
    else if (idx < 360448) prep_one(Wn2, g_wimg + OFF_WN2, 128, idx - 327680);
}

// ---------------- GEMM core ---------------------------------------------------
// C[64 x NC] (acc regs) = A[64 x K](smem tf32 row-major) @ Wimg.
// 8 warps: warp_m = wid&3 (16-row strip), warp_n = wid>>2 (NC/2-col strip).
// acc: [NC/16][4] per warp. Chunks of 4096 floats double-buffered via cp.async.
template<int K, int NC>
static __device__ __forceinline__ void gemm_mma(
    const float* __restrict__ Xs, int lda,
    const float* __restrict__ img,
    float* wb0, float* wb1,
    float (*acc)[4],
    int warp_m, int warp_n, int lane, int tid)
{
    constexpr int KC  = 4096 / NC;   // k per chunk
    constexpr int S   = KC / 8;      // k8 steps per chunk
    constexpr int NCH = K / KC;
    constexpr int P   = NC / 16;     // n8-pairs per row
    constexpr int PW  = P / 2;       // pairs per warp
    const uint32_t wba0 = smem_u32(wb0), wba1 = smem_u32(wb1);

    {   // issue chunk 0
        unsigned long long src = gptr(img) + (size_t)tid * 16;
        uint32_t dst = wba0 + tid * 16;
#pragma unroll
        for (int i = 0; i < 4; i++) CP_ASYNC16(dst + i * 4096, src + (size_t)i * 4096);
        CP_COMMIT();
    }
    for (int c = 0; c < NCH; c++) {
        if (c + 1 < NCH) {
            unsigned long long src = gptr(img) + (size_t)(c + 1) * 16384 + (size_t)tid * 16;
            uint32_t dst = ((c + 1) & 1 ? wba1 : wba0) + tid * 16;
#pragma unroll
            for (int i = 0; i < 4; i++) CP_ASYNC16(dst + i * 4096, src + (size_t)i * 4096);
            CP_COMMIT();
            CP_WAIT1();
        } else {
            CP_WAIT0();
        }
        __syncthreads();
        const float* wb = (c & 1) ? wb1 : wb0;
#pragma unroll
        for (int s = 0; s < S; s++) {
            const int k0 = c * KC + s * 8;
            const float* arow = Xs + (size_t)(warp_m * 16 + (lane >> 2)) * lda + k0 + (lane & 3);
            uint32_t a[4];
            a[0] = __float_as_uint(arow[0]);
            a[1] = __float_as_uint(arow[8 * lda]);
            a[2] = __float_as_uint(arow[4]);
            a[3] = __float_as_uint(arow[8 * lda + 4]);
#pragma unroll
            for (int pp = 0; pp < PW; pp++) {
                const float4 b = *(const float4*)&wb[((s * P) + warp_n * PW + pp) * 128 + lane * 4];
                mma_tf32(acc[2 * pp],     a, __float_as_uint(b.x), __float_as_uint(b.y));
                mma_tf32(acc[2 * pp + 1], a, __float_as_uint(b.z), __float_as_uint(b.w));
            }
        }
        __syncthreads();
    }
}

// ---------------- edge kernel --------------------------------------------------
#define XS_LDA 388
#define HS_LDA 260
// floats: Xs[0,24832) Hs[24832,41472) WB0[41472,45568) WB1[45568,49664)
//         rcv@49664 snd@49728 ae@49792  -> total 49856 floats = 199424 B
#define E_SMEM_BYTES (49856 * 4)

__global__ void __launch_bounds__(THREADS, 1) edge_kernel(
    const float* __restrict__ nodes, const float* __restrict__ edges,
    const int* __restrict__ senders, const int* __restrict__ receivers,
    const float* __restrict__ active_edges,
    const float* __restrict__ be1, const float* __restrict__ be2,
    const float* __restrict__ bf1, const float* __restrict__ bf2,
    float* __restrict__ out_edges, int E)
{
    extern __shared__ float sm[];
    float* Xs  = sm;
    float* Hs  = sm + 24832;
    float* WB0 = sm + 41472;
    float* WB1 = sm + 45568;
    int*   rcv = (int*)(sm + 49664);
    int*   snd = (int*)(sm + 49728);
    float* ae  = sm + 49792;

    const int tid = threadIdx.x;
    const int lane = tid & 31, wid = tid >> 5;
    const int warp_m = wid & 3, warp_n = wid >> 2;
    const int cbase = (lane & 3) * 2;
    const long long e0 = (long long)blockIdx.x * 64;

    if (tid < 64) {
        long long er = e0 + tid;
        bool ok = er < E;
        rcv[tid] = ok ? receivers[er] : 0;
        snd[tid] = ok ? senders[er] : 0;
        ae[tid]  = ok ? active_edges[er] : 0.f;
    }
    __syncthreads();

    // gather X = [e | h_recv | h_send], tf32, row-major lda=388
    {
        const float4* E4 = (const float4*)edges;
        const float4* N4 = (const float4*)nodes;
        float4 z = make_float4(0.f, 0.f, 0.f, 0.f);
        for (int idx = tid; idx < 64 * 96; idx += THREADS) {
            int r = idx / 96, c4 = idx - (idx / 96) * 96;
            long long er = e0 + r;
            bool ok = er < E;
            float4 v;
            if (c4 < 32)      v = ok ? E4[(size_t)er * 32 + c4] : z;
            else if (c4 < 64) v = ok ? N4[(size_t)rcv[r] * 32 + (c4 - 32)] : z;
            else              v = ok ? N4[(size_t)snd[r] * 32 + (c4 - 64)] : z;
            v.x = cvt_tf32_f(v.x); v.y = cvt_tf32_f(v.y);
            v.z = cvt_tf32_f(v.z); v.w = cvt_tf32_f(v.w);
            *(float4*)&Xs[(size_t)r * XS_LDA + c4 * 4] = v;
        }
    }
    // gemm_mma syncs internally before first use of Xs

    const int r = warp_m * 16 + (lane >> 2);

    // --- GEMM1: H1 = relu(X @ We1 + be1) ---
    {
        float acc[16][4];
#pragma unroll
        for (int t = 0; t < 16; t++)
#pragma unroll
            for (int q = 0; q < 4; q++) acc[t][q] = 0.f;
        gemm_mma<384, 256>(Xs, XS_LDA, g_wimg + OFF_WE1, WB0, WB1, acc,
                           warp_m, warp_n, lane, tid);
#pragma unroll
        for (int t = 0; t < 16; t++) {
            int n0 = warp_n * 128 + t * 8 + cbase;
            float b0 = __ldg(be1 + n0), b1 = __ldg(be1 + n0 + 1);
            float2 lo = make_float2(cvt_tf32_f(fmaxf(acc[t][0] + b0, 0.f)),
                                    cvt_tf32_f(fmaxf(acc[t][1] + b1, 0.f)));
            float2 hi = make_float2(cvt_tf32_f(fmaxf(acc[t][2] + b0, 0.f)),
                                    cvt_tf32_f(fmaxf(acc[t][3] + b1, 0.f)));
            *(float2*)&Hs[(size_t)r * HS_LDA + n0]       = lo;
            *(float2*)&Hs[(size_t)(r + 8) * HS_LDA + n0] = hi;
        }
    }

    // --- GEMM2: edges_new = (H1 @ We2 + be2) * ae ; store + rewrite Xs[:,0:128) ---
    {
        float acc[8][4];
#pragma unroll
        for (int t = 0; t < 8; t++)
#pragma unroll
            for (int q = 0; q < 4; q++) acc[t][q] = 0.f;
        gemm_mma<256, 128>(Hs, HS_LDA, g_wimg + OFF_WE2, WB0, WB1, acc,
                           warp_m, warp_n, lane, tid);
        long long er0 = e0 + r;
        float m0 = ae[r], m1 = ae[r + 8];
        bool ok0 = er0 < E, ok1 = (er0 + 8) < E;
#pragma unroll
        for (int t = 0; t < 8; t++) {
            int n0 = warp_n * 64 + t * 8 + cbase;
            float b0 = __ldg(be2 + n0), b1 = __ldg(be2 + n0 + 1);
            float v00 = (acc[t][0] + b0) * m0, v01 = (acc[t][1] + b1) * m0;
            float v10 = (acc[t][2] + b0) * m1, v11 = (acc[t][3] + b1) * m1;
            if (ok0) *(float2*)&out_edges[(size_t)er0 * 128 + n0] = make_float2(v00, v01);
            if (ok1) *(float2*)&out_edges[(size_t)(er0 + 8) * 128 + n0] = make_float2(v10, v11);
            *(float2*)&Xs[(size_t)r * XS_LDA + n0] =
                make_float2(cvt_tf32_f(v00), cvt_tf32_f(v01));
            *(float2*)&Xs[(size_t)(r + 8) * XS_LDA + n0] =
                make_float2(cvt_tf32_f(v10), cvt_tf32_f(v11));
        }
    }

    // --- GEMM3: H2 = relu(F @ Wf1 + bf1) ---
    {
        float acc[16][4];
#pragma unroll
        for (int t = 0; t < 16; t++)
#pragma unroll
            for (int q = 0; q < 4; q++) acc[t][q] = 0.f;
        gemm_mma<384, 256>(Xs, XS_LDA, g_wimg + OFF_WF1, WB0, WB1, acc,
                           warp_m, warp_n, lane, tid);
#pragma unroll
        for (int t = 0; t < 16; t++) {
            int n0 = warp_n * 128 + t * 8 + cbase;
            float b0 = __ldg(bf1 + n0), b1 = __ldg(bf1 + n0 + 1);
            float2 lo = make_float2(cvt_tf32_f(fmaxf(acc[t][0] + b0, 0.f)),
                                    cvt_tf32_f(fmaxf(acc[t][1] + b1, 0.f)));
            float2 hi = make_float2(cvt_tf32_f(fmaxf(acc[t][2] + b0, 0.f)),
                                    cvt_tf32_f(fmaxf(acc[t][3] + b1, 0.f)));
            *(float2*)&Hs[(size_t)r * HS_LDA + n0]       = lo;
            *(float2*)&Hs[(size_t)(r + 8) * HS_LDA + n0] = hi;
        }
    }

    // --- GEMM4: effects = H2 @ Wf2 + bf2 ; atomicAdd into g_agg[recv] ---
    {
        float acc[8][4];
#pragma unroll
        for (int t = 0; t < 8; t++)
#pragma unroll
            for (int q = 0; q < 4; q++) acc[t][q] = 0.f;
        gemm_mma<256, 128>(Hs, HS_LDA, g_wimg + OFF_WF2, WB0, WB1, acc,
                           warp_m, warp_n, lane, tid);
        long long er0 = e0 + r;
        bool ok0 = er0 < E, ok1 = (er0 + 8) < E;
        float* a0p = g_agg + (size_t)rcv[r] * 128;
        float* a1p = g_agg + (size_t)rcv[r + 8] * 128;
#pragma unroll
        for (int t = 0; t < 8; t++) {
            int n0 = warp_n * 64 + t * 8 + cbase;
            float b0 = __ldg(bf2 + n0), b1 = __ldg(bf2 + n0 + 1);
            if (ok0) {
                atomicAdd(a0p + n0,     acc[t][0] + b0);
                atomicAdd(a0p + n0 + 1, acc[t][1] + b1);
            }
            if (ok1) {
                atomicAdd(a1p + n0,     acc[t][2] + b0);
                atomicAdd(a1p + n0 + 1, acc[t][3] + b1);
            }
        }
    }
}

// ---------------- node kernel ---------------------------------------------------
// floats: Xs[0,16640) Hs[16640,33280) WB0[33280,37376) WB1[37376,41472)
//         act@41472 -> total 41536 floats = 166144 B
#define N_SMEM_BYTES (41536 * 4)

__global__ void __launch_bounds__(THREADS, 1) node_kernel(
    const float* __restrict__ nodes, const float* __restrict__ active_nodes,
    const float* __restrict__ bn1, const float* __restrict__ bn2,
    float* __restrict__ out_nodes, int N)
{
    extern __shared__ float sm[];
    float* Xs  = sm;
    float* Hs  = sm + 16640;
    float* WB0 = sm + 33280;
    float* WB1 = sm + 37376;
    float* act = sm + 41472;

    const int tid = threadIdx.x;
    const int lane = tid & 31, wid = tid >> 5;
    const int warp_m = wid & 3, warp_n = wid >> 2;
    const int cbase = (lane & 3) * 2;
    const long long n0r = (long long)blockIdx.x * 64;

    if (tid < 64) {
        long long row = n0r + tid;
        act[tid] = (row < N) ? active_nodes[row] : 0.f;
    }

    {   // gather Y = [nodes | agg], tf32, lda=260
        const float4* N4 = (const float4*)nodes;
        const float4* A4 = (const float4*)g_agg;
        float4 z = make_float4(0.f, 0.f, 0.f, 0.f);
        for (int idx = tid; idx < 64 * 64; idx += THREADS) {
            int rr = idx >> 6, c4 = idx & 63;
            long long row = n0r + rr;
            bool ok = row < N;
            float4 v;
            if (c4 < 32) v = ok ? N4[(size_t)row * 32 + c4] : z;
            else         v = ok ? A4[(size_t)row * 32 + (c4 - 32)] : z;
            v.x = cvt_tf32_f(v.x); v.y = cvt_tf32_f(v.y);
            v.z = cvt_tf32_f(v.z); v.w = cvt_tf32_f(v.w);
            *(float4*)&Xs[(size_t)rr * HS_LDA + c4 * 4] = v;
        }
    }

    const int r = warp_m * 16 + (lane >> 2);

    {
        float acc[16][4];
#pragma unroll
        for (int t = 0; t < 16; t++)
#pragma unroll
            for (int q = 0; q < 4; q++) acc[t][q] = 0.f;
        gemm_mma<256, 256>(Xs, HS_LDA, g_wimg + OFF_WN1, WB0, WB1, acc,
                           warp_m, warp_n, lane, tid);
#pragma unroll
        for (int t = 0; t < 16; t++) {
            int n0 = warp_n * 128 + t * 8 + cbase;
            float b0 = __ldg(bn1 + n0), b1 = __ldg(bn1 + n0 + 1);
            float2 lo = make_float2(cvt_tf32_f(fmaxf(acc[t][0] + b0, 0.f)),
                                    cvt_tf32_f(fmaxf(acc[t][1] + b1, 0.f)));
            float2 hi = make_float2(cvt_tf32_f(fmaxf(acc[t][2] + b0, 0.f)),
                                    cvt_tf32_f(fmaxf(acc[t][3] + b1, 0.f)));
            *(float2*)&Hs[(size_t)r * HS_LDA + n0]       = lo;
            *(float2*)&Hs[(size_t)(r + 8) * HS_LDA + n0] = hi;
        }
    }
    {
        float acc[8][4];
#pragma unroll
        for (int t = 0; t < 8; t++)
#pragma unroll
            for (int q = 0; q < 4; q++) acc[t][q] = 0.f;
        gemm_mma<256, 128>(Hs, HS_LDA, g_wimg + OFF_WN2, WB0, WB1, acc,
                           warp_m, warp_n, lane, tid);
        long long row0 = n0r + r;
        bool ok0 = row0 < N, ok1 = (row0 + 8) < N;
        float m0 = act[r], m1 = act[r + 8];
#pragma unroll
        for (int t = 0; t < 8; t++) {
            int n0 = warp_n * 64 + t * 8 + cbase;
            float b0 = __ldg(bn2 + n0), b1 = __ldg(bn2 + n0 + 1);
            if (ok0) {
                float2 base = *(const float2*)&nodes[(size_t)row0 * 128 + n0];
                *(float2*)&out_nodes[(size_t)row0 * 128 + n0] =
                    make_float2(base.x + (acc[t][0] + b0) * m0,
                                base.y + (acc[t][1] + b1) * m0);
            }
            if (ok1) {
                float2 base = *(const float2*)&nodes[(size_t)(row0 + 8) * 128 + n0];
                *(float2*)&out_nodes[(size_t)(row0 + 8) * 128 + n0] =
                    make_float2(base.x + (acc[t][2] + b0) * m1,
                                base.y + (acc[t][3] + b1) * m1);
            }
        }
    }
}

// ---------------- launch ---------------------------------------------------------
extern "C" void kernel_launch(void* const* d_in, const int* in_sizes, int n_in,
                              void* d_out, int out_size)
{
    const float* nodes        = (const float*)d_in[0];
    const float* edges        = (const float*)d_in[1];
    const int*   senders      = (const int*)d_in[2];
    const int*   receivers    = (const int*)d_in[3];
    const float* active_nodes = (const float*)d_in[4];
    const float* active_edges = (const float*)d_in[5];
    const float* We1 = (const float*)d_in[6];
    const float* be1 = (const float*)d_in[7];
    const float* We2 = (const float*)d_in[8];
    const float* be2 = (const float*)d_in[9];
    const float* Wf1 = (const float*)d_in[10];
    const float* bf1 = (const float*)d_in[11];
    const float* Wf2 = (const float*)d_in[12];
    const float* bf2 = (const float*)d_in[13];
    const float* Wn1 = (const float*)d_in[14];
    const float* bn1 = (const float*)d_in[15];
    const float* Wn2 = (const float*)d_in[16];
    const float* bn2 = (const float*)d_in[17];

    const int E = in_sizes[2];
    const int N = in_sizes[4];

    float* out_nodes = (float*)d_out;
    float* out_edges = out_nodes + (size_t)N * 128;

    cudaFuncSetAttribute(edge_kernel, cudaFuncAttributeMaxDynamicSharedMemorySize, E_SMEM_BYTES);
    cudaFuncSetAttribute(node_kernel, cudaFuncAttributeMaxDynamicSharedMemorySize, N_SMEM_BYTES);

    prep_zero_kernel<<<4096, 256>>>(We1, We2, Wf1, Wf2, Wn1, Wn2, N * 128 / 4);

    int eblocks = (E + 63) / 64;
    edge_kernel<<<eblocks, THREADS, E_SMEM_BYTES>>>(
        nodes, edges, senders, receivers, active_edges,
        be1, be2, bf1, bf2, out_edges, E);

    int nblocks = (N + 63) / 64;
    node_kernel<<<nblocks, THREADS, N_SMEM_BYTES>>>(
        nodes, active_nodes, bn1, bn2, out_nodes, N);
}

// round 5
// speedup vs baseline: 11.4946x; 2.1348x over previous
#include <cuda_runtime.h>
#include <cuda_fp16.h>
#include <cstdint>

// ============================================================================
// IGNN step via mma.sync.m16n8k16 f16 (f32 accum). 128 edges/CTA, 512 threads
// (16 warps: 4 m-strips x 4 n-strips). X/H tiles in smem as fp16; weights
// pre-packed fragment-major fp16 in g_wimg, cp.async double-buffered.
// ============================================================================

#define THREADS 512
#define NN 50000
#define XLDA 392   // halves; (XLDA/2) % 32 == 4 -> conflict-free A frags
#define HLDA 264

// image offsets in halves
#define OFF_WE1 0
#define OFF_WE2 98304
#define OFF_WF1 131072
#define OFF_WF2 229376
#define OFF_WN1 262144
#define OFF_WN2 327680
#define WIMG_TOTAL 360448

__device__ __align__(16) __half g_wimg[WIMG_TOTAL];
__device__ float g_agg[(size_t)NN * 128];

static __device__ __forceinline__ uint32_t smem_u32(const void* p) {
    uint32_t a;
    asm("{ .reg .u64 t; cvta.to.shared.u64 t, %1; cvt.u32.u64 %0, t; }"
        : "=r"(a) : "l"(p));
    return a;
}
static __device__ __forceinline__ unsigned long long gptr(const void* p) {
    unsigned long long g;
    asm("cvta.to.global.u64 %0, %1;" : "=l"(g) : "l"(p));
    return g;
}

#define CP_ASYNC16(dst, src) \
    asm volatile("cp.async.cg.shared.global [%0], [%1], 16;" :: "r"(dst), "l"(src))
#define CP_COMMIT() asm volatile("cp.async.commit_group;" ::: "memory")
#define CP_WAIT1()  asm volatile("cp.async.wait_group 1;" ::: "memory")
#define CP_WAIT0()  asm volatile("cp.async.wait_group 0;" ::: "memory")

static __device__ __forceinline__ void mma_f16(float (&d)[4], const uint32_t (&a)[4],
                                               uint32_t b0, uint32_t b1) {
    asm volatile(
        "mma.sync.aligned.m16n8k16.row.col.f32.f16.f16.f32 "
        "{%0,%1,%2,%3}, {%4,%5,%6,%7}, {%8,%9}, {%0,%1,%2,%3};"
        : "+f"(d[0]), "+f"(d[1]), "+f"(d[2]), "+f"(d[3])
        : "r"(a[0]), "r"(a[1]), "r"(a[2]), "r"(a[3]), "r"(b0), "r"(b1));
}
static __device__ __forceinline__ uint32_t packh2(float x, float y) {
    __half2 h = __floats2half2_rn(x, y);
    return *(uint32_t*)&h;
}

// ---------------- prep: fragment-major fp16 weight image + zero agg ----------
// Block = 512 B = 32 lanes x 8 halves: lane holds, for n16 pair pp at k16 step s:
//   h0,h1 = B[k0+2c, k0+2c+1][n0]        (b0 of even n8 tile)
//   h2,h3 = B[k0+2c+8, +9][n0]           (b1)
//   h4..7 = same with n0+8               (odd n8 tile)
// k0 = s*16, c = lane&3, n0 = pp*16 + (lane>>2).
static __device__ __forceinline__ void prep_one_h(const float* __restrict__ W,
                                                  __half* __restrict__ dst,
                                                  int NC, int g) {
    int lane = g & 31, blk = g >> 5;
    int P2 = NC / 16;
    int pp = blk % P2, s = blk / P2;
    int k0 = s * 16 + 2 * (lane & 3);
    int n0 = pp * 16 + (lane >> 2);
    __half h[8];
#pragma unroll
    for (int t = 0; t < 2; t++) {
        int n = n0 + t * 8;
        h[4*t+0] = __float2half_rn(W[(size_t)(k0    ) * NC + n]);
        h[4*t+1] = __float2half_rn(W[(size_t)(k0 + 1) * NC + n]);
        h[4*t+2] = __float2half_rn(W[(size_t)(k0 + 8) * NC + n]);
        h[4*t+3] = __float2half_rn(W[(size_t)(k0 + 9) * NC + n]);
    }
    *(uint4*)&dst[(size_t)g * 8] = *(uint4*)h;
}

__global__ void prep_zero_kernel(
    const float* We1, const float* We2, const float* Wf1,
    const float* Wf2, const float* Wn1, const float* Wn2, int nfour)
{
    int idx = blockIdx.x * blockDim.x + threadIdx.x;
    float4 z = make_float4(0.f, 0.f, 0.f, 0.f);
    for (int i = idx; i < nfour; i += gridDim.x * blockDim.x)
        ((float4*)g_agg)[i] = z;
    if (idx < 12288)       prep_one_h(We1, g_wimg + OFF_WE1, 256, idx);
    else if (idx < 16384)  prep_one_h(We2, g_wimg + OFF_WE2, 128, idx - 12288);
    else if (idx < 28672)  prep_one_h(Wf1, g_wimg + OFF_WF1, 256, idx - 16384);
    else if (idx < 32768)  prep_one_h(Wf2, g_wimg + OFF_WF2, 128, idx - 28672);
    else if (idx < 40960)  prep_one_h(Wn1, g_wimg + OFF_WN1, 256, idx - 32768);
    else if (idx < 45056)  prep_one_h(Wn2, g_wimg + OFF_WN2, 128, idx - 40960);
}

// ---------------- GEMM core: C[128 x NC] = A[128 x K] @ W -------------------
// 16 warps: warp_m = wid&3 (32-row strip, 2 m16 tiles), warp_n = wid>>2
// (NC/4 cols). acc[mt*NT+nt][4]. Chunks of 8192 halves (16KB) double-buffered.
template<int K, int NC>
static __device__ __forceinline__ void gemm_h(
    const __half* __restrict__ Xs, int lda,
    const __half* __restrict__ img,
    __half* wb0, __half* wb1,
    float (*acc)[4],
    int warp_m, int warp_n, int lane, int tid)
{
    constexpr int KC  = 8192 / NC;    // k per chunk (32 or 64)
    constexpr int S   = KC / 16;      // k16 steps per chunk
    constexpr int NCH = K / KC;
    constexpr int P2  = NC / 16;      // n16 pairs per k-step
    constexpr int PW  = P2 / 4;       // pairs per warp
    const uint32_t wba0 = smem_u32(wb0), wba1 = smem_u32(wb1);

    {   // chunk 0
        unsigned long long src = gptr(img) + (size_t)tid * 16;
        uint32_t dst = wba0 + tid * 16;
        CP_ASYNC16(dst, src);
        CP_ASYNC16(dst + 8192, src + 8192);
        CP_COMMIT();
    }
    for (int c = 0; c < NCH; c++) {
        if (c + 1 < NCH) {
            unsigned long long src = gptr(img + (size_t)(c + 1) * 8192) + (size_t)tid * 16;
            uint32_t dst = (((c + 1) & 1) ? wba1 : wba0) + tid * 16;
            CP_ASYNC16(dst, src);
            CP_ASYNC16(dst + 8192, src + 8192);
            CP_COMMIT();
            CP_WAIT1();
        } else {
            CP_WAIT0();
        }
        __syncthreads();
        const __half* wb = (c & 1) ? wb1 : wb0;
#pragma unroll
        for (int s = 0; s < S; s++) {
            const int kb = c * KC + s * 16 + 2 * (lane & 3);
            uint32_t a[2][4];
#pragma unroll
            for (int mt = 0; mt < 2; mt++) {
                const __half* ar = Xs + (size_t)(warp_m * 32 + mt * 16 + (lane >> 2)) * lda + kb;
                a[mt][0] = *(const uint32_t*)(ar);
                a[mt][1] = *(const uint32_t*)(ar + 8 * lda);
                a[mt][2] = *(const uint32_t*)(ar + 8);
                a[mt][3] = *(const uint32_t*)(ar + 8 * lda + 8);
            }
#pragma unroll
            for (int pp = 0; pp < PW; pp++) {
                const uint4 b = *(const uint4*)&wb[((size_t)(s * P2 + warp_n * PW + pp)) * 256 + lane * 8];
#pragma unroll
                for (int mt = 0; mt < 2; mt++) {
                    mma_f16(acc[mt * 2 * PW + 2 * pp],     a[mt], b.x, b.y);
                    mma_f16(acc[mt * 2 * PW + 2 * pp + 1], a[mt], b.z, b.w);
                }
            }
        }
        __syncthreads();
    }
}

// ---------------- edge kernel -------------------------------------------------
// halves: Xs[0,50176) Hs[50176,83968) WB0[83968,92160) WB1[92160,100352)
// rcv@100352h snd@100608h ae@100864h -> 101120 halves = 202240 B
#define E_SMEM_BYTES (101120 * 2)

__global__ void __launch_bounds__(THREADS, 1) edge_kernel(
    const float* __restrict__ nodes, const float* __restrict__ edges,
    const int* __restrict__ senders, const int* __restrict__ receivers,
    const float* __restrict__ active_edges,
    const float* __restrict__ be1, const float* __restrict__ be2,
    const float* __restrict__ bf1, const float* __restrict__ bf2,
    float* __restrict__ out_edges, int E)
{
    extern __shared__ __half sm[];
    __half* Xs  = sm;
    __half* Hs  = sm + 50176;
    __half* WB0 = sm + 83968;
    __half* WB1 = sm + 92160;
    int*    rcv = (int*)(sm + 100352);
    int*    snd = (int*)(sm + 100608);
    float*  ae  = (float*)(sm + 100864);

    const int tid = threadIdx.x;
    const int lane = tid & 31, wid = tid >> 5;
    const int warp_m = wid & 3, warp_n = wid >> 2;
    const int cbase = 2 * (lane & 3);
    const long long e0 = (long long)blockIdx.x * 128;

    if (tid < 128) {
        long long er = e0 + tid;
        bool ok = er < E;
        rcv[tid] = ok ? receivers[er] : 0;
        snd[tid] = ok ? senders[er] : 0;
        ae[tid]  = ok ? active_edges[er] : 0.f;
    }
    __syncthreads();

    // gather X = [e | h_recv | h_send] -> fp16, row-major lda=392
    {
        const float4* E4 = (const float4*)edges;
        const float4* N4 = (const float4*)nodes;
        float4 z = make_float4(0.f, 0.f, 0.f, 0.f);
        for (int idx = tid; idx < 128 * 96; idx += THREADS) {
            int r = idx / 96, c4 = idx - r * 96;
            long long er = e0 + r;
            bool ok = er < E;
            float4 v;
            if (c4 < 32)      v = ok ? E4[(size_t)er * 32 + c4] : z;
            else if (c4 < 64) v = ok ? N4[(size_t)rcv[r] * 32 + (c4 - 32)] : z;
            else              v = ok ? N4[(size_t)snd[r] * 32 + (c4 - 64)] : z;
            *(uint2*)&Xs[(size_t)r * XLDA + c4 * 4] =
                make_uint2(packh2(v.x, v.y), packh2(v.z, v.w));
        }
    }
    // gemm_h syncs internally before first compute

    const int rbase = warp_m * 32 + (lane >> 2);

    // --- GEMM1: H1 = relu(X @ We1 + be1) ---
    {
        float acc[16][4];
#pragma unroll
        for (int t = 0; t < 16; t++) { acc[t][0]=0.f; acc[t][1]=0.f; acc[t][2]=0.f; acc[t][3]=0.f; }
        gemm_h<384, 256>(Xs, XLDA, g_wimg + OFF_WE1, WB0, WB1, acc, warp_m, warp_n, lane, tid);
#pragma unroll
        for (int mt = 0; mt < 2; mt++) {
            int r0 = rbase + mt * 16;
#pragma unroll
            for (int nt = 0; nt < 8; nt++) {
                int n0 = (warp_n * 8 + nt) * 8 + cbase;
                float b0 = __ldg(be1 + n0), b1 = __ldg(be1 + n0 + 1);
                float (&a)[4] = acc[mt * 8 + nt];
                *(uint32_t*)&Hs[(size_t)r0 * HLDA + n0] =
                    packh2(fmaxf(a[0] + b0, 0.f), fmaxf(a[1] + b1, 0.f));
                *(uint32_t*)&Hs[(size_t)(r0 + 8) * HLDA + n0] =
                    packh2(fmaxf(a[2] + b0, 0.f), fmaxf(a[3] + b1, 0.f));
            }
        }
    }

    // --- GEMM2: edges_new = (H1 @ We2 + be2) * ae ; store fp32 + rewrite Xs ---
    {
        float acc[8][4];
#pragma unroll
        for (int t = 0; t < 8; t++) { acc[t][0]=0.f; acc[t][1]=0.f; acc[t][2]=0.f; acc[t][3]=0.f; }
        gemm_h<256, 128>(Hs, HLDA, g_wimg + OFF_WE2, WB0, WB1, acc, warp_m, warp_n, lane, tid);
#pragma unroll
        for (int mt = 0; mt < 2; mt++) {
            int r0 = rbase + mt * 16;
            long long er0 = e0 + r0;
            float m0 = ae[r0], m1 = ae[r0 + 8];
            bool ok0 = er0 < E, ok1 = (er0 + 8) < E;
#pragma unroll
            for (int nt = 0; nt < 4; nt++) {
                int n0 = (warp_n * 4 + nt) * 8 + cbase;
                float b0 = __ldg(be2 + n0), b1 = __ldg(be2 + n0 + 1);
                float (&a)[4] = acc[mt * 4 + nt];
                float v00 = (a[0] + b0) * m0, v01 = (a[1] + b1) * m0;
                float v10 = (a[2] + b0) * m1, v11 = (a[3] + b1) * m1;
                if (ok0) *(float2*)&out_edges[(size_t)er0 * 128 + n0] = make_float2(v00, v01);
                if (ok1) *(float2*)&out_edges[(size_t)(er0 + 8) * 128 + n0] = make_float2(v10, v11);
                *(uint32_t*)&Xs[(size_t)r0 * XLDA + n0]       = packh2(v00, v01);
                *(uint32_t*)&Xs[(size_t)(r0 + 8) * XLDA + n0] = packh2(v10, v11);
            }
        }
    }

    // --- GEMM3: H2 = relu(F @ Wf1 + bf1) ---
    {
        float acc[16][4];
#pragma unroll
        for (int t = 0; t < 16; t++) { acc[t][0]=0.f; acc[t][1]=0.f; acc[t][2]=0.f; acc[t][3]=0.f; }
        gemm_h<384, 256>(Xs, XLDA, g_wimg + OFF_WF1, WB0, WB1, acc, warp_m, warp_n, lane, tid);
#pragma unroll
        for (int mt = 0; mt < 2; mt++) {
            int r0 = rbase + mt * 16;
#pragma unroll
            for (int nt = 0; nt < 8; nt++) {
                int n0 = (warp_n * 8 + nt) * 8 + cbase;
                float b0 = __ldg(bf1 + n0), b1 = __ldg(bf1 + n0 + 1);
                float (&a)[4] = acc[mt * 8 + nt];
                *(uint32_t*)&Hs[(size_t)r0 * HLDA + n0] =
                    packh2(fmaxf(a[0] + b0, 0.f), fmaxf(a[1] + b1, 0.f));
                *(uint32_t*)&Hs[(size_t)(r0 + 8) * HLDA + n0] =
                    packh2(fmaxf(a[2] + b0, 0.f), fmaxf(a[3] + b1, 0.f));
            }
        }
    }

    // --- GEMM4: effects = H2 @ Wf2 + bf2 ; atomicAdd into g_agg[recv] ---
    {
        float acc[8][4];
#pragma unroll
        for (int t = 0; t < 8; t++) { acc[t][0]=0.f; acc[t][1]=0.f; acc[t][2]=0.f; acc[t][3]=0.f; }
        gemm_h<256, 128>(Hs, HLDA, g_wimg + OFF_WF2, WB0, WB1, acc, warp_m, warp_n, lane, tid);
#pragma unroll
        for (int mt = 0; mt < 2; mt++) {
            int r0 = rbase + mt * 16;
            long long er0 = e0 + r0;
            bool ok0 = er0 < E, ok1 = (er0 + 8) < E;
            float* a0p = g_agg + (size_t)rcv[r0] * 128;
            float* a1p = g_agg + (size_t)rcv[r0 + 8] * 128;
#pragma unroll
            for (int nt = 0; nt < 4; nt++) {
                int n0 = (warp_n * 4 + nt) * 8 + cbase;
                float b0 = __ldg(bf2 + n0), b1 = __ldg(bf2 + n0 + 1);
                float (&a)[4] = acc[mt * 4 + nt];
                if (ok0) {
                    atomicAdd(a0p + n0,     a[0] + b0);
                    atomicAdd(a0p + n0 + 1, a[1] + b1);
                }
                if (ok1) {
                    atomicAdd(a1p + n0,     a[2] + b0);
                    atomicAdd(a1p + n0 + 1, a[3] + b1);
                }
            }
        }
    }
}

// ---------------- node kernel ---------------------------------------------------
// halves: Xs[0,33792) Hs[33792,67584) WB0[67584,75776) WB1[75776,83968)
// act@83968h -> 84224 halves = 168448 B
#define N_SMEM_BYTES (84224 * 2)

__global__ void __launch_bounds__(THREADS, 1) node_kernel(
    const float* __restrict__ nodes, const float* __restrict__ active_nodes,
    const float* __restrict__ bn1, const float* __restrict__ bn2,
    float* __restrict__ out_nodes, int N)
{
    extern __shared__ __half sm[];
    __half* Xs  = sm;
    __half* Hs  = sm + 33792;
    __half* WB0 = sm + 67584;
    __half* WB1 = sm + 75776;
    float*  act = (float*)(sm + 83968);

    const int tid = threadIdx.x;
    const int lane = tid & 31, wid = tid >> 5;
    const int warp_m = wid & 3, warp_n = wid >> 2;
    const int cbase = 2 * (lane & 3);
    const long long n0r = (long long)blockIdx.x * 128;

    if (tid < 128) {
        long long row = n0r + tid;
        act[tid] = (row < N) ? active_nodes[row] : 0.f;
    }
    __syncthreads();

    {   // gather Y = [nodes | agg] -> fp16, lda=264
        const float4* N4 = (const float4*)nodes;
        const float4* A4 = (const float4*)g_agg;
        float4 z = make_float4(0.f, 0.f, 0.f, 0.f);
        for (int idx = tid; idx < 128 * 64; idx += THREADS) {
            int r = idx >> 6, c4 = idx & 63;
            long long row = n0r + r;
            bool ok = row < N;
            float4 v;
            if (c4 < 32) v = ok ? N4[(size_t)row * 32 + c4] : z;
            else         v = ok ? A4[(size_t)row * 32 + (c4 - 32)] : z;
            *(uint2*)&Xs[(size_t)r * HLDA + c4 * 4] =
                make_uint2(packh2(v.x, v.y), packh2(v.z, v.w));
        }
    }

    const int rbase = warp_m * 32 + (lane >> 2);

    {
        float acc[16][4];
#pragma unroll
        for (int t = 0; t < 16; t++) { acc[t][0]=0.f; acc[t][1]=0.f; acc[t][2]=0.f; acc[t][3]=0.f; }
        gemm_h<256, 256>(Xs, HLDA, g_wimg + OFF_WN1, WB0, WB1, acc, warp_m, warp_n, lane, tid);
#pragma unroll
        for (int mt = 0; mt < 2; mt++) {
            int r0 = rbase + mt * 16;
#pragma unroll
            for (int nt = 0; nt < 8; nt++) {
                int n0 = (warp_n * 8 + nt) * 8 + cbase;
                float b0 = __ldg(bn1 + n0), b1 = __ldg(bn1 + n0 + 1);
                float (&a)[4] = acc[mt * 8 + nt];
                *(uint32_t*)&Hs[(size_t)r0 * HLDA + n0] =
                    packh2(fmaxf(a[0] + b0, 0.f), fmaxf(a[1] + b1, 0.f));
                *(uint32_t*)&Hs[(size_t)(r0 + 8) * HLDA + n0] =
                    packh2(fmaxf(a[2] + b0, 0.f), fmaxf(a[3] + b1, 0.f));
            }
        }
    }
    {
        float acc[8][4];
#pragma unroll
        for (int t = 0; t < 8; t++) { acc[t][0]=0.f; acc[t][1]=0.f; acc[t][2]=0.f; acc[t][3]=0.f; }
        gemm_h<256, 128>(Hs, HLDA, g_wimg + OFF_WN2, WB0, WB1, acc, warp_m, warp_n, lane, tid);
#pragma unroll
        for (int mt = 0; mt < 2; mt++) {
            int r0 = rbase + mt * 16;
            long long row0 = n0r + r0;
            bool ok0 = row0 < N, ok1 = (row0 + 8) < N;
            float m0 = act[r0], m1 = act[r0 + 8];
#pragma unroll
            for (int nt = 0; nt < 4; nt++) {
                int n0 = (warp_n * 4 + nt) * 8 + cbase;
                float b0 = __ldg(bn2 + n0), b1 = __ldg(bn2 + n0 + 1);
                float (&a)[4] = acc[mt * 4 + nt];
                if (ok0) {
                    float2 base = *(const float2*)&nodes[(size_t)row0 * 128 + n0];
                    *(float2*)&out_nodes[(size_t)row0 * 128 + n0] =
                        make_float2(base.x + (a[0] + b0) * m0,
                                    base.y + (a[1] + b1) * m0);
                }
                if (ok1) {
                    float2 base = *(const float2*)&nodes[(size_t)(row0 + 8) * 128 + n0];
                    *(float2*)&out_nodes[(size_t)(row0 + 8) * 128 + n0] =
                        make_float2(base.x + (a[2] + b0) * m1,
                                    base.y + (a[3] + b1) * m1);
                }
            }
        }
    }
}

// ---------------- launch ---------------------------------------------------------
extern "C" void kernel_launch(void* const* d_in, const int* in_sizes, int n_in,
                              void* d_out, int out_size)
{
    const float* nodes        = (const float*)d_in[0];
    const float* edges        = (const float*)d_in[1];
    const int*   senders      = (const int*)d_in[2];
    const int*   receivers    = (const int*)d_in[3];
    const float* active_nodes = (const float*)d_in[4];
    const float* active_edges = (const float*)d_in[5];
    const float* We1 = (const float*)d_in[6];
    const float* be1 = (const float*)d_in[7];
    const float* We2 = (const float*)d_in[8];
    const float* be2 = (const float*)d_in[9];
    const float* Wf1 = (const float*)d_in[10];
    const float* bf1 = (const float*)d_in[11];
    const float* Wf2 = (const float*)d_in[12];
    const float* bf2 = (const float*)d_in[13];
    const float* Wn1 = (const float*)d_in[14];
    const float* bn1 = (const float*)d_in[15];
    const float* Wn2 = (const float*)d_in[16];
    const float* bn2 = (const float*)d_in[17];

    const int E = in_sizes[2];
    const int N = in_sizes[4];

    float* out_nodes = (float*)d_out;
    float* out_edges = out_nodes + (size_t)N * 128;

    cudaFuncSetAttribute(edge_kernel, cudaFuncAttributeMaxDynamicSharedMemorySize, E_SMEM_BYTES);
    cudaFuncSetAttribute(node_kernel, cudaFuncAttributeMaxDynamicSharedMemorySize, N_SMEM_BYTES);

    prep_zero_kernel<<<4096, 256>>>(We1, We2, Wf1, Wf2, Wn1, Wn2, N * 128 / 4);

    int eblocks = (E + 127) / 128;
    edge_kernel<<<eblocks, THREADS, E_SMEM_BYTES>>>(
        nodes, edges, senders, receivers, active_edges,
        be1, be2, bf1, bf2, out_edges, E);

    int nblocks = (N + 127) / 128;
    node_kernel<<<nblocks, THREADS, N_SMEM_BYTES>>>(
        nodes, active_nodes, bn1, bn2, out_nodes, N);
}

// round 6
// speedup vs baseline: 15.8478x; 1.3787x over previous
#include <cuda_runtime.h>
#include <cuda_fp16.h>
#include <cstdint>

// ============================================================================
// IGNN step via mma.sync.m16n8k16 f16 (f32 accum). 64 edges/CTA, 256 threads
// (8 warps: 2 m-strips x 4 n-strips), smem 109KB -> 2 CTAs/SM. Weight chunks
// (8KB) triple-buffered cp.async, prefetch distance 2, ONE sync per chunk.
// ============================================================================

#define THREADS 256
#define NN 50000
#define XLDA 392   // halves; row stride 196 words ≡ 4 mod 32 -> conflict-free
#define HLDA 264   // 132 words ≡ 4 mod 32

// image offsets in halves (fragment-major, same layout as R5)
#define OFF_WE1 0
#define OFF_WE2 98304
#define OFF_WF1 131072
#define OFF_WF2 229376
#define OFF_WN1 262144
#define OFF_WN2 327680
#define WIMG_TOTAL 360448

__device__ __align__(16) __half g_wimg[WIMG_TOTAL];
__device__ float g_agg[(size_t)NN * 128];

static __device__ __forceinline__ uint32_t smem_u32(const void* p) {
    uint32_t a;
    asm("{ .reg .u64 t; cvta.to.shared.u64 t, %1; cvt.u32.u64 %0, t; }"
        : "=r"(a) : "l"(p));
    return a;
}
static __device__ __forceinline__ unsigned long long gptr(const void* p) {
    unsigned long long g;
    asm("cvta.to.global.u64 %0, %1;" : "=l"(g) : "l"(p));
    return g;
}

#define CP_ASYNC16(dst, src) \
    asm volatile("cp.async.cg.shared.global [%0], [%1], 16;" :: "r"(dst), "l"(src))
#define CP_COMMIT() asm volatile("cp.async.commit_group;" ::: "memory")
#define CP_WAIT1()  asm volatile("cp.async.wait_group 1;" ::: "memory")
#define CP_WAIT0()  asm volatile("cp.async.wait_group 0;" ::: "memory")

static __device__ __forceinline__ void mma_f16(float (&d)[4], const uint32_t (&a)[4],
                                               uint32_t b0, uint32_t b1) {
    asm volatile(
        "mma.sync.aligned.m16n8k16.row.col.f32.f16.f16.f32 "
        "{%0,%1,%2,%3}, {%4,%5,%6,%7}, {%8,%9}, {%0,%1,%2,%3};"
        : "+f"(d[0]), "+f"(d[1]), "+f"(d[2]), "+f"(d[3])
        : "r"(a[0]), "r"(a[1]), "r"(a[2]), "r"(a[3]), "r"(b0), "r"(b1));
}
static __device__ __forceinline__ uint32_t packh2(float x, float y) {
    __half2 h = __floats2half2_rn(x, y);
    return *(uint32_t*)&h;
}

// ---------------- prep: fragment-major fp16 weight image + zero agg ----------
static __device__ __forceinline__ void prep_one_h(const float* __restrict__ W,
                                                  __half* __restrict__ dst,
                                                  int NC, int g) {
    int lane = g & 31, blk = g >> 5;
    int P2 = NC / 16;
    int pp = blk % P2, s = blk / P2;
    int k0 = s * 16 + 2 * (lane & 3);
    int n0 = pp * 16 + (lane >> 2);
    __half h[8];
#pragma unroll
    for (int t = 0; t < 2; t++) {
        int n = n0 + t * 8;
        h[4*t+0] = __float2half_rn(W[(size_t)(k0    ) * NC + n]);
        h[4*t+1] = __float2half_rn(W[(size_t)(k0 + 1) * NC + n]);
        h[4*t+2] = __float2half_rn(W[(size_t)(k0 + 8) * NC + n]);
        h[4*t+3] = __float2half_rn(W[(size_t)(k0 + 9) * NC + n]);
    }
    *(uint4*)&dst[(size_t)g * 8] = *(uint4*)h;
}

__global__ void prep_zero_kernel(
    const float* We1, const float* We2, const float* Wf1,
    const float* Wf2, const float* Wn1, const float* Wn2, int nfour)
{
    int idx = blockIdx.x * blockDim.x + threadIdx.x;
    float4 z = make_float4(0.f, 0.f, 0.f, 0.f);
    for (int i = idx; i < nfour; i += gridDim.x * blockDim.x)
        ((float4*)g_agg)[i] = z;
    if (idx < 12288)       prep_one_h(We1, g_wimg + OFF_WE1, 256, idx);
    else if (idx < 16384)  prep_one_h(We2, g_wimg + OFF_WE2, 128, idx - 12288);
    else if (idx < 28672)  prep_one_h(Wf1, g_wimg + OFF_WF1, 256, idx - 16384);
    else if (idx < 32768)  prep_one_h(Wf2, g_wimg + OFF_WF2, 128, idx - 28672);
    else if (idx < 40960)  prep_one_h(Wn1, g_wimg + OFF_WN1, 256, idx - 32768);
    else if (idx < 45056)  prep_one_h(Wn2, g_wimg + OFF_WN2, 128, idx - 40960);
}

// ---------------- GEMM core: C[64 x NC] = A[64 x K] @ W ----------------------
// 8 warps: warp_m = wid&1 (32-row strip, 2 m16 tiles), warp_n = wid>>1
// (NC/4-col strip). acc[mt*2*PW + j][4]. 8KB chunks, 3 buffers, prefetch 2,
// ONE __syncthreads per chunk + one trailing sync.
template<int K, int NC>
static __device__ __forceinline__ void gemm_h(
    const __half* __restrict__ Xs, int lda,
    const __half* __restrict__ img, __half* wb3,
    float (*acc)[4], int warp_m, int warp_n, int lane, int tid)
{
    constexpr int KC  = 4096 / NC;    // k per 8KB chunk
    constexpr int S   = KC / 16;      // k16 steps per chunk
    constexpr int NCH = K / KC;
    constexpr int P2  = NC / 16;
    constexpr int PW  = NC / 64;      // n16 pairs per warp
    const uint32_t wba = smem_u32(wb3);

    {   // prefetch chunks 0 and 1
        unsigned long long s0 = gptr(img) + (size_t)tid * 16;
        CP_ASYNC16(wba + tid * 16, s0);
        CP_ASYNC16(wba + tid * 16 + 4096, s0 + 4096);
        CP_COMMIT();
        if (NCH > 1) {
            CP_ASYNC16(wba + 8192 + tid * 16, s0 + 8192);
            CP_ASYNC16(wba + 8192 + tid * 16 + 4096, s0 + 12288);
            CP_COMMIT();
        }
    }
    for (int c = 0; c < NCH; c++) {
        if (c == NCH - 1) { CP_WAIT0(); } else { CP_WAIT1(); }
        __syncthreads();   // chunk c visible to all; buffer (c+2)%3 free to refill
        if (c + 2 < NCH) {
            int b = (c + 2) % 3;
            unsigned long long s = gptr(img) + (size_t)(c + 2) * 8192 + (size_t)tid * 16;
            CP_ASYNC16(wba + b * 8192 + tid * 16, s);
            CP_ASYNC16(wba + b * 8192 + tid * 16 + 4096, s + 4096);
            CP_COMMIT();
        }
        const __half* wb = wb3 + (size_t)(c % 3) * 4096;
#pragma unroll
        for (int sl = 0; sl < S; sl++) {
            const int kb = c * KC + sl * 16 + 2 * (lane & 3);
            uint32_t a[2][4];
#pragma unroll
            for (int mt = 0; mt < 2; mt++) {
                const __half* ar = Xs + (size_t)(warp_m * 32 + mt * 16 + (lane >> 2)) * lda + kb;
                a[mt][0] = *(const uint32_t*)(ar);
                a[mt][1] = *(const uint32_t*)(ar + 8 * lda);
                a[mt][2] = *(const uint32_t*)(ar + 8);
                a[mt][3] = *(const uint32_t*)(ar + 8 * lda + 8);
            }
#pragma unroll
            for (int pp = 0; pp < PW; pp++) {
                const uint4 b = *(const uint4*)&wb[(size_t)(sl * P2 + warp_n * PW + pp) * 256 + lane * 8];
#pragma unroll
                for (int mt = 0; mt < 2; mt++) {
                    mma_f16(acc[mt * 2 * PW + 2 * pp],     a[mt], b.x, b.y);
                    mma_f16(acc[mt * 2 * PW + 2 * pp + 1], a[mt], b.z, b.w);
                }
            }
        }
    }
    __syncthreads();   // all reads of Xs/wb3 done before caller reuses smem
}

// ---------------- edge kernel -------------------------------------------------
// halves: Xs[0,25088) Hs[25088,41984) WB3[41984,54272)
//         rcv@54272 snd@54400 ae@54528 -> 54656 halves = 109312 B
#define E_SMEM_BYTES (54656 * 2)

__global__ void __launch_bounds__(THREADS, 2) edge_kernel(
    const float* __restrict__ nodes, const float* __restrict__ edges,
    const int* __restrict__ senders, const int* __restrict__ receivers,
    const float* __restrict__ active_edges,
    const float* __restrict__ be1, const float* __restrict__ be2,
    const float* __restrict__ bf1, const float* __restrict__ bf2,
    float* __restrict__ out_edges, int E)
{
    extern __shared__ __half sm[];
    __half* Xs  = sm;
    __half* Hs  = sm + 25088;
    __half* WB3 = sm + 41984;
    int*    rcv = (int*)(sm + 54272);
    int*    snd = (int*)(sm + 54400);
    float*  ae  = (float*)(sm + 54528);

    const int tid = threadIdx.x;
    const int lane = tid & 31, wid = tid >> 5;
    const int warp_m = wid & 1, warp_n = wid >> 1;
    const int cbase = 2 * (lane & 3);
    const long long e0 = (long long)blockIdx.x * 64;

    if (tid < 64) {
        long long er = e0 + tid;
        bool ok = er < E;
        rcv[tid] = ok ? receivers[er] : 0;
        snd[tid] = ok ? senders[er] : 0;
        ae[tid]  = ok ? active_edges[er] : 0.f;
    }
    __syncthreads();

    // gather X = [e | h_recv | h_send] -> fp16, row-major lda=392
    {
        const float4* E4 = (const float4*)edges;
        const float4* N4 = (const float4*)nodes;
        float4 z = make_float4(0.f, 0.f, 0.f, 0.f);
        for (int idx = tid; idx < 64 * 96; idx += THREADS) {
            int r = idx / 96, c4 = idx - r * 96;
            long long er = e0 + r;
            bool ok = er < E;
            float4 v;
            if (c4 < 32)      v = ok ? E4[(size_t)er * 32 + c4] : z;
            else if (c4 < 64) v = ok ? N4[(size_t)rcv[r] * 32 + (c4 - 32)] : z;
            else              v = ok ? N4[(size_t)snd[r] * 32 + (c4 - 64)] : z;
            *(uint2*)&Xs[(size_t)r * XLDA + c4 * 4] =
                make_uint2(packh2(v.x, v.y), packh2(v.z, v.w));
        }
    }
    // gemm_h syncs before first compute

    const int rA = warp_m * 32 + (lane >> 2);   // +mt*16, +8 variants

    // --- GEMM1: H1 = relu(X @ We1 + be1) ---
    {
        float acc[16][4];
#pragma unroll
        for (int t = 0; t < 16; t++) { acc[t][0]=0.f; acc[t][1]=0.f; acc[t][2]=0.f; acc[t][3]=0.f; }
        gemm_h<384, 256>(Xs, XLDA, g_wimg + OFF_WE1, WB3, acc, warp_m, warp_n, lane, tid);
#pragma unroll
        for (int mt = 0; mt < 2; mt++) {
            int r0 = rA + mt * 16;
#pragma unroll
            for (int j = 0; j < 8; j++) {
                int n0 = warp_n * 64 + j * 8 + cbase;
                float b0 = __ldg(be1 + n0), b1 = __ldg(be1 + n0 + 1);
                float (&a)[4] = acc[mt * 8 + j];
                *(uint32_t*)&Hs[(size_t)r0 * HLDA + n0] =
                    packh2(fmaxf(a[0] + b0, 0.f), fmaxf(a[1] + b1, 0.f));
                *(uint32_t*)&Hs[(size_t)(r0 + 8) * HLDA + n0] =
                    packh2(fmaxf(a[2] + b0, 0.f), fmaxf(a[3] + b1, 0.f));
            }
        }
    }

    // --- GEMM2: edges_new = (H1 @ We2 + be2) * ae ; store fp32 + rewrite Xs ---
    {
        float acc[8][4];
#pragma unroll
        for (int t = 0; t < 8; t++) { acc[t][0]=0.f; acc[t][1]=0.f; acc[t][2]=0.f; acc[t][3]=0.f; }
        gemm_h<256, 128>(Hs, HLDA, g_wimg + OFF_WE2, WB3, acc, warp_m, warp_n, lane, tid);
#pragma unroll
        for (int mt = 0; mt < 2; mt++) {
            int r0 = rA + mt * 16;
            long long er0 = e0 + r0;
            float m0 = ae[r0], m1 = ae[r0 + 8];
            bool ok0 = er0 < E, ok1 = (er0 + 8) < E;
#pragma unroll
            for (int j = 0; j < 4; j++) {
                int n0 = warp_n * 32 + j * 8 + cbase;
                float b0 = __ldg(be2 + n0), b1 = __ldg(be2 + n0 + 1);
                float (&a)[4] = acc[mt * 4 + j];
                float v00 = (a[0] + b0) * m0, v01 = (a[1] + b1) * m0;
                float v10 = (a[2] + b0) * m1, v11 = (a[3] + b1) * m1;
                if (ok0) *(float2*)&out_edges[(size_t)er0 * 128 + n0] = make_float2(v00, v01);
                if (ok1) *(float2*)&out_edges[(size_t)(er0 + 8) * 128 + n0] = make_float2(v10, v11);
                *(uint32_t*)&Xs[(size_t)r0 * XLDA + n0]       = packh2(v00, v01);
                *(uint32_t*)&Xs[(size_t)(r0 + 8) * XLDA + n0] = packh2(v10, v11);
            }
        }
    }

    // --- GEMM3: H2 = relu(F @ Wf1 + bf1) ---
    {
        float acc[16][4];
#pragma unroll
        for (int t = 0; t < 16; t++) { acc[t][0]=0.f; acc[t][1]=0.f; acc[t][2]=0.f; acc[t][3]=0.f; }
        gemm_h<384, 256>(Xs, XLDA, g_wimg + OFF_WF1, WB3, acc, warp_m, warp_n, lane, tid);
#pragma unroll
        for (int mt = 0; mt < 2; mt++) {
            int r0 = rA + mt * 16;
#pragma unroll
            for (int j = 0; j < 8; j++) {
                int n0 = warp_n * 64 + j * 8 + cbase;
                float b0 = __ldg(bf1 + n0), b1 = __ldg(bf1 + n0 + 1);
                float (&a)[4] = acc[mt * 8 + j];
                *(uint32_t*)&Hs[(size_t)r0 * HLDA + n0] =
                    packh2(fmaxf(a[0] + b0, 0.f), fmaxf(a[1] + b1, 0.f));
                *(uint32_t*)&Hs[(size_t)(r0 + 8) * HLDA + n0] =
                    packh2(fmaxf(a[2] + b0, 0.f), fmaxf(a[3] + b1, 0.f));
            }
        }
    }

    // --- GEMM4: effects = H2 @ Wf2 + bf2 ; atomicAdd into g_agg[recv] ---
    {
        float acc[8][4];
#pragma unroll
        for (int t = 0; t < 8; t++) { acc[t][0]=0.f; acc[t][1]=0.f; acc[t][2]=0.f; acc[t][3]=0.f; }
        gemm_h<256, 128>(Hs, HLDA, g_wimg + OFF_WF2, WB3, acc, warp_m, warp_n, lane, tid);
#pragma unroll
        for (int mt = 0; mt < 2; mt++) {
            int r0 = rA + mt * 16;
            long long er0 = e0 + r0;
            bool ok0 = er0 < E, ok1 = (er0 + 8) < E;
            float* a0p = g_agg + (size_t)rcv[r0] * 128;
            float* a1p = g_agg + (size_t)rcv[r0 + 8] * 128;
#pragma unroll
            for (int j = 0; j < 4; j++) {
                int n0 = warp_n * 32 + j * 8 + cbase;
                float b0 = __ldg(bf2 + n0), b1 = __ldg(bf2 + n0 + 1);
                float (&a)[4] = acc[mt * 4 + j];
                if (ok0) {
                    atomicAdd(a0p + n0,     a[0] + b0);
                    atomicAdd(a0p + n0 + 1, a[1] + b1);
                }
                if (ok1) {
                    atomicAdd(a1p + n0,     a[2] + b0);
                    atomicAdd(a1p + n0 + 1, a[3] + b1);
                }
            }
        }
    }
}

// ---------------- node kernel ---------------------------------------------------
// halves: Xs[0,16896) Hs[16896,33792) WB3[33792,46080) act@46080 -> 46208 h
#define N_SMEM_BYTES (46208 * 2)

__global__ void __launch_bounds__(THREADS, 2) node_kernel(
    const float* __restrict__ nodes, const float* __restrict__ active_nodes,
    const float* __restrict__ bn1, const float* __restrict__ bn2,
    float* __restrict__ out_nodes, int N)
{
    extern __shared__ __half sm[];
    __half* Xs  = sm;
    __half* Hs  = sm + 16896;
    __half* WB3 = sm + 33792;
    float*  act = (float*)(sm + 46080);

    const int tid = threadIdx.x;
    const int lane = tid & 31, wid = tid >> 5;
    const int warp_m = wid & 1, warp_n = wid >> 1;
    const int cbase = 2 * (lane & 3);
    const long long n0r = (long long)blockIdx.x * 64;

    if (tid < 64) {
        long long row = n0r + tid;
        act[tid] = (row < N) ? active_nodes[row] : 0.f;
    }
    __syncthreads();

    {   // gather Y = [nodes | agg] -> fp16, lda=264
        const float4* N4 = (const float4*)nodes;
        const float4* A4 = (const float4*)g_agg;
        float4 z = make_float4(0.f, 0.f, 0.f, 0.f);
        for (int idx = tid; idx < 64 * 64; idx += THREADS) {
            int r = idx >> 6, c4 = idx & 63;
            long long row = n0r + r;
            bool ok = row < N;
            float4 v;
            if (c4 < 32) v = ok ? N4[(size_t)row * 32 + c4] : z;
            else         v = ok ? A4[(size_t)row * 32 + (c4 - 32)] : z;
            *(uint2*)&Xs[(size_t)r * HLDA + c4 * 4] =
                make_uint2(packh2(v.x, v.y), packh2(v.z, v.w));
        }
    }

    const int rA = warp_m * 32 + (lane >> 2);

    {
        float acc[16][4];
#pragma unroll
        for (int t = 0; t < 16; t++) { acc[t][0]=0.f; acc[t][1]=0.f; acc[t][2]=0.f; acc[t][3]=0.f; }
        gemm_h<256, 256>(Xs, HLDA, g_wimg + OFF_WN1, WB3, acc, warp_m, warp_n, lane, tid);
#pragma unroll
        for (int mt = 0; mt < 2; mt++) {
            int r0 = rA + mt * 16;
#pragma unroll
            for (int j = 0; j < 8; j++) {
                int n0 = warp_n * 64 + j * 8 + cbase;
                float b0 = __ldg(bn1 + n0), b1 = __ldg(bn1 + n0 + 1);
                float (&a)[4] = acc[mt * 8 + j];
                *(uint32_t*)&Hs[(size_t)r0 * HLDA + n0] =
                    packh2(fmaxf(a[0] + b0, 0.f), fmaxf(a[1] + b1, 0.f));
                *(uint32_t*)&Hs[(size_t)(r0 + 8) * HLDA + n0] =
                    packh2(fmaxf(a[2] + b0, 0.f), fmaxf(a[3] + b1, 0.f));
            }
        }
    }
    {
        float acc[8][4];
#pragma unroll
        for (int t = 0; t < 8; t++) { acc[t][0]=0.f; acc[t][1]=0.f; acc[t][2]=0.f; acc[t][3]=0.f; }
        gemm_h<256, 128>(Hs, HLDA, g_wimg + OFF_WN2, WB3, acc, warp_m, warp_n, lane, tid);
#pragma unroll
        for (int mt = 0; mt < 2; mt++) {
            int r0 = rA + mt * 16;
            long long row0 = n0r + r0;
            bool ok0 = row0 < N, ok1 = (row0 + 8) < N;
            float m0 = act[r0], m1 = act[r0 + 8];
#pragma unroll
            for (int j = 0; j < 4; j++) {
                int n0 = warp_n * 32 + j * 8 + cbase;
                float b0 = __ldg(bn2 + n0), b1 = __ldg(bn2 + n0 + 1);
                float (&a)[4] = acc[mt * 4 + j];
                if (ok0) {
                    float2 base = *(const float2*)&nodes[(size_t)row0 * 128 + n0];
                    *(float2*)&out_nodes[(size_t)row0 * 128 + n0] =
                        make_float2(base.x + (a[0] + b0) * m0,
                                    base.y + (a[1] + b1) * m0);
                }
                if (ok1) {
                    float2 base = *(const float2*)&nodes[(size_t)(row0 + 8) * 128 + n0];
                    *(float2*)&out_nodes[(size_t)(row0 + 8) * 128 + n0] =
                        make_float2(base.x + (a[2] + b0) * m1,
                                    base.y + (a[3] + b1) * m1);
                }
            }
        }
    }
}

// ---------------- launch ---------------------------------------------------------
extern "C" void kernel_launch(void* const* d_in, const int* in_sizes, int n_in,
                              void* d_out, int out_size)
{
    const float* nodes        = (const float*)d_in[0];
    const float* edges        = (const float*)d_in[1];
    const int*   senders      = (const int*)d_in[2];
    const int*   receivers    = (const int*)d_in[3];
    const float* active_nodes = (const float*)d_in[4];
    const float* active_edges = (const float*)d_in[5];
    const float* We1 = (const float*)d_in[6];
    const float* be1 = (const float*)d_in[7];
    const float* We2 = (const float*)d_in[8];
    const float* be2 = (const float*)d_in[9];
    const float* Wf1 = (const float*)d_in[10];
    const float* bf1 = (const float*)d_in[11];
    const float* Wf2 = (const float*)d_in[12];
    const float* bf2 = (const float*)d_in[13];
    const float* Wn1 = (const float*)d_in[14];
    const float* bn1 = (const float*)d_in[15];
    const float* Wn2 = (const float*)d_in[16];
    const float* bn2 = (const float*)d_in[17];

    const int E = in_sizes[2];
    const int N = in_sizes[4];

    float* out_nodes = (float*)d_out;
    float* out_edges = out_nodes + (size_t)N * 128;

    cudaFuncSetAttribute(edge_kernel, cudaFuncAttributeMaxDynamicSharedMemorySize, E_SMEM_BYTES);
    cudaFuncSetAttribute(node_kernel, cudaFuncAttributeMaxDynamicSharedMemorySize, N_SMEM_BYTES);

    prep_zero_kernel<<<4096, 256>>>(We1, We2, Wf1, Wf2, Wn1, Wn2, N * 128 / 4);

    int eblocks = (E + 63) / 64;
    edge_kernel<<<eblocks, THREADS, E_SMEM_BYTES>>>(
        nodes, edges, senders, receivers, active_edges,
        be1, be2, bf1, bf2, out_edges, E);

    int nblocks = (N + 63) / 64;
    node_kernel<<<nblocks, THREADS, N_SMEM_BYTES>>>(
        nodes, active_nodes, bn1, bn2, out_nodes, N);
}